// round 14
// baseline (speedup 1.0000x reference)
#include <cuda_runtime.h>
#include <cstdint>

// Problem constants
#define BATCHX 8
#define NSEQ   1024
#define EMBD   1024
#define HEADS  16
#define DHEAD  64
#define KDIM   1024
#define MROWS  (BATCHX * NSEQ)   // 8192

// Scratch (device globals: allocation-free per harness rules)
__device__ float g_q[BATCHX * HEADS * NSEQ * DHEAD];
__device__ float g_k[BATCHX * HEADS * NSEQ * DHEAD];
__device__ float g_v[BATCHX * HEADS * NSEQ * DHEAD];
__device__ float g_att[MROWS * EMBD];
__device__ float g_xr[MROWS * EMBD];          // tf32-rounded x
__device__ float g_wqr[3 * EMBD * EMBD];      // tf32-rounded W_qkv
__device__ float g_wor[EMBD * EMBD];          // tf32-rounded W_out
__device__ float g_bias[HEADS * NSEQ * NSEQ]; // expanded bias table (64MB)

__device__ __forceinline__ uint32_t smem_u32(const void* p) {
    uint32_t a;
    asm("{ .reg .u64 t; cvta.to.shared.u64 t, %1; cvt.u32.u64 %0, t; }"
        : "=r"(a) : "l"(p));
    return a;
}

__device__ __forceinline__ uint32_t f2tf32(float x) {
    uint32_t y;
    asm("cvt.rna.tf32.f32 %0, %1;" : "=r"(y) : "f"(x));
    return y;
}

__device__ __forceinline__ void mma_tf32(float* c, const uint32_t* a, const uint32_t* b) {
    asm volatile(
        "mma.sync.aligned.m16n8k8.row.col.f32.tf32.tf32.f32 "
        "{%0,%1,%2,%3}, {%4,%5,%6,%7}, {%8,%9}, {%0,%1,%2,%3};"
        : "+f"(c[0]), "+f"(c[1]), "+f"(c[2]), "+f"(c[3])
        : "r"(a[0]), "r"(a[1]), "r"(a[2]), "r"(a[3]), "r"(b[0]), "r"(b[1]));
}

__device__ __forceinline__ void ldsm4(uint32_t* r, uint32_t addr) {
    asm volatile("ldmatrix.sync.aligned.m8n8.x4.shared.b16 {%0,%1,%2,%3}, [%4];"
                 : "=r"(r[0]), "=r"(r[1]), "=r"(r[2]), "=r"(r[3]) : "r"(addr));
}

__device__ __forceinline__ void cpa16(uint32_t dst, const void* src) {
    asm volatile("cp.async.cg.shared.global [%0], [%1], 16;" :: "r"(dst), "l"(src));
}

// ---------------------------------------------------------------------------
// Fused tf32 pre-round pass: x (2M float4) + W_qkv (768K) + W_out (256K)
// ---------------------------------------------------------------------------
#define N4_X  (MROWS * EMBD / 4)
#define N4_WQ (3 * EMBD * EMBD / 4)
#define N4_WO (EMBD * EMBD / 4)

__global__ __launch_bounds__(256) void round_all_kernel(const float4* __restrict__ x,
                                                        const float4* __restrict__ wq,
                                                        const float4* __restrict__ wo,
                                                        float4* __restrict__ xr,
                                                        float4* __restrict__ wqr,
                                                        float4* __restrict__ wor) {
    const int i = blockIdx.x * 256 + threadIdx.x;
    const float4* s;
    float4* d;
    int k;
    if (i < N4_X) { s = x; d = xr; k = i; }
    else if (i < N4_X + N4_WQ) { s = wq; d = wqr; k = i - N4_X; }
    else { s = wo; d = wor; k = i - N4_X - N4_WQ; }
    const float4 v = s[k];
    uint4 w;
    w.x = f2tf32(v.x); w.y = f2tf32(v.y); w.z = f2tf32(v.z); w.w = f2tf32(v.w);
    d[k] = *(const float4*)&w;
}

// ---------------------------------------------------------------------------
// Bias expansion: g_bias[h][i][j] = biases[h][idxs[i][j]]
// ---------------------------------------------------------------------------
__global__ __launch_bounds__(256) void bias_expand_kernel(const float* __restrict__ biases,
                                                          const int* __restrict__ idxs) {
    const size_t t = (size_t)blockIdx.x * 256 + threadIdx.x;   // 4M threads
    const int j = (int)(t & 255) * 4;
    const int i = (int)(t >> 8) & 1023;
    const int h = (int)(t >> 18);
    const int4 id = *(const int4*)&idxs[(size_t)i * NSEQ + j];
    const float* brow = biases + h * 1024;
    float4 o;
    o.x = __ldg(&brow[id.x]);
    o.y = __ldg(&brow[id.y]);
    o.z = __ldg(&brow[id.z]);
    o.w = __ldg(&brow[id.w]);
    *(float4*)&g_bias[((size_t)h << 20) + (size_t)i * NSEQ + j] = o;
}

// ===========================================================================
// tf32 GEMM: cp.async 3-stage ring + ldmatrix, BK=32. (unchanged from R7)
// ===========================================================================
#define STG_BYTES 32768   // per stage: A 16KB + B 16KB

__device__ __forceinline__ uint32_t offG(int row, int u) {
    return (uint32_t)(row * 128 + ((u ^ (row & 7)) << 4));
}

__device__ __forceinline__ void tf32_mainloop_ca(const float* __restrict__ A,
                                                 const float* __restrict__ B,
                                                 int m0, int n0, char* sm,
                                                 float acc[4][4][4]) {
    const int tid = threadIdx.x;
    const int lane = tid & 31;
    const int wid = tid >> 5;
    const int wm = wid >> 2, wn = wid & 3;
    const uint32_t sb = smem_u32(sm);

    const int lrow = tid >> 3, lu = tid & 7;
    uint32_t oT[4];
    const float* ap[4];
    const float* bp[4];
#pragma unroll
    for (int i = 0; i < 4; i++) {
        const int row = lrow + 32 * i;
        oT[i] = offG(row, lu);
        ap[i] = A + (size_t)(m0 + row) * KDIM + lu * 4;
        bp[i] = B + (size_t)(n0 + row) * KDIM + lu * 4;
    }

#pragma unroll
    for (int i = 0; i < 4; i++)
#pragma unroll
        for (int j = 0; j < 4; j++)
#pragma unroll
            for (int r = 0; r < 4; r++) acc[i][j][r] = 0.f;

    const int sub = lane >> 3;
    const int arow = 64 * wm + (lane & 7) + ((sub & 1) << 3);
    const int aub = sub >> 1;
    const int brow = 32 * wn + (lane & 7) + ((sub >> 1) << 3);
    const int bub = sub & 1;
    const int asw = arow & 7;
    const int bsw = brow & 7;

#define G_ISSUE(st, p)                                                         \
    do {                                                                       \
        const int ko = (st) * 32;                                              \
        const uint32_t bb_ = sb + (uint32_t)(p) * STG_BYTES;                   \
        cpa16(bb_ + oT[0], ap[0] + ko);                                        \
        cpa16(bb_ + oT[1], ap[1] + ko);                                        \
        cpa16(bb_ + oT[2], ap[2] + ko);                                        \
        cpa16(bb_ + oT[3], ap[3] + ko);                                        \
        cpa16(bb_ + 16384 + oT[0], bp[0] + ko);                                \
        cpa16(bb_ + 16384 + oT[1], bp[1] + ko);                                \
        cpa16(bb_ + 16384 + oT[2], bp[2] + ko);                                \
        cpa16(bb_ + 16384 + oT[3], bp[3] + ko);                                \
    } while (0)

    G_ISSUE(0, 0);
    asm volatile("cp.async.commit_group;");
    G_ISSUE(1, 1);
    asm volatile("cp.async.commit_group;");

    const int NST = KDIM / 32;   // 32
    int p = 0;
    for (int st = 0; st < NST; st++) {
        asm volatile("cp.async.wait_group 1;");
        __syncthreads();
        const uint32_t abase = sb + (uint32_t)p * STG_BYTES;
        const uint32_t bbase = abase + 16384;
#pragma unroll
        for (int s = 0; s < 4; s++) {
            uint32_t af[4][4];
            uint32_t bf[4][2];
#pragma unroll
            for (int i = 0; i < 4; i++) {
                const int row = arow + 16 * i;
                ldsm4(af[i], abase + (uint32_t)(row * 128 + (((2 * s + aub) ^ asw) << 4)));
            }
#pragma unroll
            for (int jj = 0; jj < 2; jj++) {
                uint32_t t[4];
                const int row = brow + 16 * jj;
                ldsm4(t, bbase + (uint32_t)(row * 128 + (((2 * s + bub) ^ bsw) << 4)));
                bf[2 * jj][0] = t[0]; bf[2 * jj][1] = t[1];
                bf[2 * jj + 1][0] = t[2]; bf[2 * jj + 1][1] = t[3];
            }
#pragma unroll
            for (int i = 0; i < 4; i++)
#pragma unroll
                for (int j = 0; j < 4; j++)
                    mma_tf32(acc[i][j], af[i], bf[j]);
        }
        const int nx = st + 2;
        if (nx < NST) G_ISSUE(nx, nx % 3);
        asm volatile("cp.async.commit_group;");
        p = (p + 1) % 3;
    }
#undef G_ISSUE
}

// ---------------------------------------------------------------------------
// GEMM1: qkv = xr @ Wqkv_r^T -> scatter q (pre-scaled) / k / v, tf32-rounded
// ---------------------------------------------------------------------------
__global__ __launch_bounds__(256) void qkv_gemm_mma(const float* __restrict__ A,
                                                    const float* __restrict__ W) {
    extern __shared__ char smg[];
    const int m0 = blockIdx.y * 128;
    const int n0 = blockIdx.x * 128;
    float acc[4][4][4];
    tf32_mainloop_ca(A, W, m0, n0, smg, acc);

    const int tid = threadIdx.x;
    const int lane = tid & 31;
    const int wid = tid >> 5;
    const int wm = wid >> 2, wn = wid & 3;

    const int t = n0 >> 10;              // 0=q 1=k 2=v
    const float scale = (t == 0) ? 0.125f : 1.0f;
    float* dst = (t == 0) ? g_q : ((t == 1) ? g_k : g_v);

#pragma unroll
    for (int i = 0; i < 4; i++) {
#pragma unroll
        for (int j = 0; j < 4; j++) {
#pragma unroll
            for (int hh = 0; hh < 2; hh++) {
                const int m = m0 + 64 * wm + 16 * i + (lane >> 2) + 8 * hh;
                const int n = n0 + 32 * wn + 8 * j + 2 * (lane & 3);
                const int b = m >> 10, nn = m & 1023;
                const int e = n & 1023;
                const int h = e >> 6, d = e & 63;
                float2 o;
                o.x = __uint_as_float(f2tf32(acc[i][j][2 * hh + 0] * scale));
                o.y = __uint_as_float(f2tf32(acc[i][j][2 * hh + 1] * scale));
                *(float2*)&dst[(((size_t)b * HEADS + h) * NSEQ + nn) * DHEAD + d] = o;
            }
        }
    }
}

// ---------------------------------------------------------------------------
// GEMM2: out = g_att @ Wout_r^T + b_out
// ---------------------------------------------------------------------------
__global__ __launch_bounds__(256) void out_gemm_mma(const float* __restrict__ W,
                                                    const float* __restrict__ bias,
                                                    float* __restrict__ out) {
    extern __shared__ char smg[];
    const int m0 = blockIdx.y * 128;
    const int n0 = blockIdx.x * 128;
    float acc[4][4][4];
    tf32_mainloop_ca(g_att, W, m0, n0, smg, acc);

    const int tid = threadIdx.x;
    const int lane = tid & 31;
    const int wid = tid >> 5;
    const int wm = wid >> 2, wn = wid & 3;

#pragma unroll
    for (int i = 0; i < 4; i++) {
#pragma unroll
        for (int j = 0; j < 4; j++) {
#pragma unroll
            for (int hh = 0; hh < 2; hh++) {
                const int m = m0 + 64 * wm + 16 * i + (lane >> 2) + 8 * hh;
                const int n = n0 + 32 * wn + 8 * j + 2 * (lane & 3);
                float2 o;
                o.x = acc[i][j][2 * hh + 0] + bias[n + 0];
                o.y = acc[i][j][2 * hh + 1] + bias[n + 1];
                *(float2*)&out[(size_t)m * EMBD + n] = o;
            }
        }
    }
}

// ===========================================================================
// Tensor-core flash attention, Q-tile 64 rows (2048 CTAs -> ~99% wave eff).
// 8 warps: wr = w>>1 row-group (16 rows), wk = w&1 key-half (32 keys).
// Direct exp (no max); row-sums and O combined across key-halves at the end.
// SMEM: Q 0..16K | K db 16..48K | VT 48..64K | P 64..80K | stage/lsum 64..81K
// ===========================================================================
#define ATT_Q 0u
#define ATT_K0 16384u
#define ATT_V 49152u
#define ATT_P 65536u
#define ATT_LS 82304u        // 64 floats after 64x65 stage (stage reuses ATT_P)
#define ATT_SMEM 82688

__device__ __forceinline__ uint32_t off8(int row, int u) {
    return (uint32_t)(row * 256 + ((u ^ (row & 7)) << 4));
}

__global__ __launch_bounds__(256, 2) void attn_mma() {
    extern __shared__ char smc[];
    const uint32_t sb = smem_u32(smc);
    const int tid = threadIdx.x;
    const int lane = tid & 31;
    const int w = tid >> 5;
    const int wr = w >> 1;          // row-group 0..3
    const int wk = w & 1;           // key-half 0..1
    const int g = lane >> 2;
    const int tig = lane & 3;

    const int q0 = blockIdx.x << 6;             // 64-row Q tile
    const int h = blockIdx.y & 15;
    const int b = blockIdx.y >> 4;

    const size_t bh = (size_t)(b * HEADS + h) * NSEQ * DHEAD;
    const float* qb = g_q + bh;
    const float* kb = g_k + bh;
    const float* vb = g_v + bh;

    // ---- Q tile via cp.async (once): 64 rows x 16 units ----
#pragma unroll
    for (int i = 0; i < 4; i++) {
        const int slot = tid + 256 * i;
        const int row = slot >> 4, lu = slot & 15;
        cpa16(sb + ATT_Q + off8(row, lu), qb + (size_t)(q0 + row) * DHEAD + lu * 4);
    }
    // ---- K0 in same group ----
#pragma unroll
    for (int i = 0; i < 4; i++) {
        const int slot = tid + 256 * i;
        const int row = slot >> 4, lu = slot & 15;
        cpa16(sb + ATT_K0 + off8(row, lu), kb + (size_t)row * DHEAD + lu * 4);
    }
    asm volatile("cp.async.commit_group;");
    // ---- V0 LDG -> STS (transposed) ----
#pragma unroll
    for (int i = 0; i < 4; i++) {
        const int slot = tid + 256 * i;
        const int key = slot >> 4;
        const int d0 = (slot & 15) * 4;
        const float4 vv = *(const float4*)(vb + (size_t)key * DHEAD + d0);
        const uint32_t cu = (uint32_t)(key >> 2);
        const uint32_t co = (uint32_t)((key & 3) * 4);
        *(float*)(smc + ATT_V + off8(d0 + 0, cu) + co) = vv.x;
        *(float*)(smc + ATT_V + off8(d0 + 1, cu) + co) = vv.y;
        *(float*)(smc + ATT_V + off8(d0 + 2, cu) + co) = vv.z;
        *(float*)(smc + ATT_V + off8(d0 + 3, cu) + co) = vv.w;
    }

    float oc[8][4];
#pragma unroll
    for (int u = 0; u < 8; u++)
#pragma unroll
        for (int r = 0; r < 4; r++) oc[u][r] = 0.f;
    float lsum0 = 0.f, lsum1 = 0.f;

    // dense bias rows for this thread's two c-frag rows
    const float* bt0 = g_bias + ((size_t)h << 20) + (size_t)(q0 + 16 * wr + g) * NSEQ;
    const float* bt1 = bt0 + 8 * NSEQ;

    // ldmatrix lane constants
    const int sub = lane >> 3;
    const int qrow = 16 * wr + (lane & 7) + ((sub & 1) << 3);   // Q/P a-frag rows
    const int aub = sub >> 1;
    const int qsw = qrow & 7;
    const int brow_k = 32 * wk + (lane & 7) + ((sub >> 1) << 3); // K b-frag rows (+16jj)
    const int brow_v = (lane & 7) + ((sub >> 1) << 3);           // VT b-frag rows (+16jj)
    const int bub = sub & 1;

    // P-store lane constants
    const int pr0 = 16 * wr + g;
    const int pr1 = pr0 + 8;
    const uint32_t phalf = (uint32_t)((tig & 1) * 8);

    for (int j0 = 0; j0 < NSEQ; j0 += 64) {
        const int p = (j0 >> 6) & 1;
        const uint32_t kcur = ATT_K0 + (uint32_t)p * 16384u;
        const uint32_t knxt = ATT_K0 + (uint32_t)(p ^ 1) * 16384u;
        const bool more = (j0 + 64 < NSEQ);
        if (more) {
#pragma unroll
            for (int i = 0; i < 4; i++) {
                const int slot = tid + 256 * i;
                const int row = slot >> 4, lu = slot & 15;
                cpa16(sb + knxt + off8(row, lu),
                      kb + (size_t)(j0 + 64 + row) * DHEAD + lu * 4);
            }
        }
        asm volatile("cp.async.commit_group;");
        float4 vv2[4];
        const int jv = more ? j0 + 64 : j0;
#pragma unroll
        for (int i = 0; i < 4; i++) {
            const int slot = tid + 256 * i;
            const int key = slot >> 4;
            const int d0 = (slot & 15) * 4;
            vv2[i] = *(const float4*)(vb + (size_t)(jv + key) * DHEAD + d0);
        }
        asm volatile("cp.async.wait_group 1;");
        __syncthreads();   // K(j) ready; VT(j) visible

        // ---- S = Q K^T (warp: 16 rows x 32 keys) ----
        float sc[4][4];
#pragma unroll
        for (int u = 0; u < 4; u++)
#pragma unroll
            for (int r = 0; r < 4; r++) sc[u][r] = 0.f;
#pragma unroll
        for (int s = 0; s < 8; s++) {
            uint32_t a[4];
            ldsm4(a, sb + ATT_Q + (uint32_t)(qrow * 256 + (((2 * s + aub) ^ qsw) << 4)));
            uint32_t bf[4][2];
#pragma unroll
            for (int jj = 0; jj < 2; jj++) {
                uint32_t t[4];
                const int row = brow_k + 16 * jj;
                ldsm4(t, sb + kcur + (uint32_t)(row * 256 + (((2 * s + bub) ^ (row & 7)) << 4)));
                bf[2 * jj][0] = t[0]; bf[2 * jj][1] = t[1];
                bf[2 * jj + 1][0] = t[2]; bf[2 * jj + 1][1] = t[3];
            }
#pragma unroll
            for (int u = 0; u < 4; u++) mma_tf32(sc[u], a, bf[u]);
        }

        // ---- bias + exp + partial sums + P store ----
#pragma unroll
        for (int u = 0; u < 4; u++) {
            const int cc = j0 + 32 * wk + 8 * u + 2 * tig;
            const float2 b0 = *(const float2*)(bt0 + cc);
            const float2 b1 = *(const float2*)(bt1 + cc);
            const float e0 = __expf(sc[u][0] + b0.x);
            const float e1 = __expf(sc[u][1] + b0.y);
            const float e2 = __expf(sc[u][2] + b1.x);
            const float e3 = __expf(sc[u][3] + b1.y);
            lsum0 += e0 + e1;
            lsum1 += e2 + e3;
            const int lu = 8 * wk + 2 * u + (tig >> 1);
            const uint32_t a0 = sb + ATT_P + off8(pr0, lu) + phalf;
            const uint32_t a1 = sb + ATT_P + off8(pr1, lu) + phalf;
            asm volatile("st.shared.v2.b32 [%0], {%1,%2};"
                         :: "r"(a0), "r"(f2tf32(e0)), "r"(f2tf32(e1)));
            asm volatile("st.shared.v2.b32 [%0], {%1,%2};"
                         :: "r"(a1), "r"(f2tf32(e2)), "r"(f2tf32(e3)));
        }
        __syncwarp();

        // ---- O += P V  (warp: its 32 keys, all 64 d) ----
#pragma unroll
        for (int s = 0; s < 4; s++) {
            uint32_t a[4];
            const int lu = 8 * wk + 2 * s + aub;
            ldsm4(a, sb + ATT_P + (uint32_t)(qrow * 256 + ((lu ^ qsw) << 4)));
            uint32_t bf[8][2];
#pragma unroll
            for (int jj = 0; jj < 4; jj++) {
                uint32_t t[4];
                const int row = brow_v + 16 * jj;
                const int vu = 8 * wk + 2 * s + bub;
                ldsm4(t, sb + ATT_V + (uint32_t)(row * 256 + ((vu ^ (row & 7)) << 4)));
                bf[2 * jj][0] = t[0]; bf[2 * jj][1] = t[1];
                bf[2 * jj + 1][0] = t[2]; bf[2 * jj + 1][1] = t[3];
            }
#pragma unroll
            for (int u2 = 0; u2 < 8; u2++) mma_tf32(oc[u2], a, bf[u2]);
        }
        __syncthreads();   // everyone done reading VT / P

        // ---- store prefetched V(j+1) ----
#pragma unroll
        for (int i = 0; i < 4; i++) {
            const int slot = tid + 256 * i;
            const int key = slot >> 4;
            const int d0 = (slot & 15) * 4;
            const uint32_t cu = (uint32_t)(key >> 2);
            const uint32_t co = (uint32_t)((key & 3) * 4);
            *(float*)(smc + ATT_V + off8(d0 + 0, cu) + co) = vv2[i].x;
            *(float*)(smc + ATT_V + off8(d0 + 1, cu) + co) = vv2[i].y;
            *(float*)(smc + ATT_V + off8(d0 + 2, cu) + co) = vv2[i].z;
            *(float*)(smc + ATT_V + off8(d0 + 3, cu) + co) = vv2[i].w;
        }
    }

    // ---- combine key-halves: quad-reduce, stage wk=1, add in wk=0 ----
    lsum0 += __shfl_xor_sync(0xFFFFFFFFu, lsum0, 1);
    lsum0 += __shfl_xor_sync(0xFFFFFFFFu, lsum0, 2);
    lsum1 += __shfl_xor_sync(0xFFFFFFFFu, lsum1, 1);
    lsum1 += __shfl_xor_sync(0xFFFFFFFFu, lsum1, 2);

    float* stage = (float*)(smc + ATT_P);        // [64 rows][stride 65]
    float* lsbuf = (float*)(smc + ATT_LS);       // [64]
    __syncthreads();   // all PV reads of P done before staging overwrites it

    if (wk == 1) {
#pragma unroll
        for (int u2 = 0; u2 < 8; u2++) {
            const int d = 8 * u2 + 2 * tig;
            stage[(16 * wr + g) * 65 + d]     = oc[u2][0];
            stage[(16 * wr + g) * 65 + d + 1] = oc[u2][1];
            stage[(16 * wr + g + 8) * 65 + d]     = oc[u2][2];
            stage[(16 * wr + g + 8) * 65 + d + 1] = oc[u2][3];
        }
        if (tig == 0) {
            lsbuf[16 * wr + g] = lsum0;
            lsbuf[16 * wr + g + 8] = lsum1;
        }
    }
    __syncthreads();

    if (wk == 0) {
        const float inv0 = 1.f / (lsum0 + lsbuf[16 * wr + g]);
        const float inv1 = 1.f / (lsum1 + lsbuf[16 * wr + g + 8]);
        const int row0 = q0 + 16 * wr + g;
#pragma unroll
        for (int u2 = 0; u2 < 8; u2++) {
            const int d = 8 * u2 + 2 * tig;
            float2 o0, o1;
            o0.x = __uint_as_float(f2tf32((oc[u2][0] + stage[(16 * wr + g) * 65 + d]) * inv0));
            o0.y = __uint_as_float(f2tf32((oc[u2][1] + stage[(16 * wr + g) * 65 + d + 1]) * inv0));
            o1.x = __uint_as_float(f2tf32((oc[u2][2] + stage[(16 * wr + g + 8) * 65 + d]) * inv1));
            o1.y = __uint_as_float(f2tf32((oc[u2][3] + stage[(16 * wr + g + 8) * 65 + d + 1]) * inv1));
            *(float2*)&g_att[((size_t)b * NSEQ + row0) * EMBD + h * DHEAD + d] = o0;
            *(float2*)&g_att[((size_t)b * NSEQ + row0 + 8) * EMBD + h * DHEAD + d] = o1;
        }
    }
}

// ---------------------------------------------------------------------------
extern "C" void kernel_launch(void* const* d_in, const int* in_sizes, int n_in,
                              void* d_out, int out_size) {
    (void)in_sizes; (void)n_in; (void)out_size;
    const float* x      = (const float*)d_in[0];
    const float* W_qkv  = (const float*)d_in[1];
    const float* biases = (const float*)d_in[2];
    const int*   idxs   = (const int*)d_in[3];
    const float* W_out  = (const float*)d_in[4];
    const float* b_out  = (const float*)d_in[5];
    float* out = (float*)d_out;

    float* xr;  cudaGetSymbolAddress((void**)&xr, g_xr);
    float* wqr; cudaGetSymbolAddress((void**)&wqr, g_wqr);
    float* wor; cudaGetSymbolAddress((void**)&wor, g_wor);

    const int gemm_smem = 3 * STG_BYTES;   // 96 KB
    cudaFuncSetAttribute(qkv_gemm_mma, cudaFuncAttributeMaxDynamicSharedMemorySize, gemm_smem);
    cudaFuncSetAttribute(out_gemm_mma, cudaFuncAttributeMaxDynamicSharedMemorySize, gemm_smem);
    cudaFuncSetAttribute(attn_mma, cudaFuncAttributeMaxDynamicSharedMemorySize, ATT_SMEM);

    const int n4_total = N4_X + N4_WQ + N4_WO;
    round_all_kernel<<<(n4_total + 255) / 256, 256>>>(
        (const float4*)x, (const float4*)W_qkv, (const float4*)W_out,
        (float4*)xr, (float4*)wqr, (float4*)wor);
    bias_expand_kernel<<<(HEADS * NSEQ * NSEQ / 4) / 256, 256>>>(biases, idxs);

    qkv_gemm_mma<<<dim3(24, 64), 256, gemm_smem>>>(xr, wqr);
    attn_mma<<<dim3(16, BATCHX * HEADS), 256, ATT_SMEM>>>();
    out_gemm_mma<<<dim3(8, 64), 256, gemm_smem>>>(wor, b_out, out);
}

// round 15
// speedup vs baseline: 1.1051x; 1.1051x over previous
#include <cuda_runtime.h>
#include <cstdint>

// Problem constants
#define BATCHX 8
#define NSEQ   1024
#define EMBD   1024
#define HEADS  16
#define DHEAD  64
#define KDIM   1024
#define MROWS  (BATCHX * NSEQ)   // 8192

// Scratch (device globals: allocation-free per harness rules)
__device__ float g_q[BATCHX * HEADS * NSEQ * DHEAD];
__device__ float g_k[BATCHX * HEADS * NSEQ * DHEAD];
__device__ float g_v[BATCHX * HEADS * NSEQ * DHEAD];
__device__ float g_att[MROWS * EMBD];
__device__ float g_xr[MROWS * EMBD];
__device__ float g_wqr[3 * EMBD * EMBD];
__device__ float g_wor[EMBD * EMBD];
__device__ float g_bias[HEADS * NSEQ * NSEQ];

__device__ __forceinline__ uint32_t smem_u32(const void* p) {
    uint32_t a;
    asm("{ .reg .u64 t; cvta.to.shared.u64 t, %1; cvt.u32.u64 %0, t; }"
        : "=r"(a) : "l"(p));
    return a;
}

__device__ __forceinline__ uint32_t f2tf32(float x) {
    uint32_t y;
    asm("cvt.rna.tf32.f32 %0, %1;" : "=r"(y) : "f"(x));
    return y;
}

__device__ __forceinline__ void mma_tf32(float* c, const uint32_t* a, const uint32_t* b) {
    asm volatile(
        "mma.sync.aligned.m16n8k8.row.col.f32.tf32.tf32.f32 "
        "{%0,%1,%2,%3}, {%4,%5,%6,%7}, {%8,%9}, {%0,%1,%2,%3};"
        : "+f"(c[0]), "+f"(c[1]), "+f"(c[2]), "+f"(c[3])
        : "r"(a[0]), "r"(a[1]), "r"(a[2]), "r"(a[3]), "r"(b[0]), "r"(b[1]));
}

__device__ __forceinline__ void ldsm4(uint32_t* r, uint32_t addr) {
    asm volatile("ldmatrix.sync.aligned.m8n8.x4.shared.b16 {%0,%1,%2,%3}, [%4];"
                 : "=r"(r[0]), "=r"(r[1]), "=r"(r[2]), "=r"(r[3]) : "r"(addr));
}

__device__ __forceinline__ void cpa16(uint32_t dst, const void* src) {
    asm volatile("cp.async.cg.shared.global [%0], [%1], 16;" :: "r"(dst), "l"(src));
}

// ---------------------------------------------------------------------------
// Fused tf32 pre-round pass
// ---------------------------------------------------------------------------
#define N4_X  (MROWS * EMBD / 4)
#define N4_WQ (3 * EMBD * EMBD / 4)
#define N4_WO (EMBD * EMBD / 4)

__global__ __launch_bounds__(256) void round_all_kernel(const float4* __restrict__ x,
                                                        const float4* __restrict__ wq,
                                                        const float4* __restrict__ wo,
                                                        float4* __restrict__ xr,
                                                        float4* __restrict__ wqr,
                                                        float4* __restrict__ wor) {
    const int i = blockIdx.x * 256 + threadIdx.x;
    const float4* s;
    float4* d;
    int k;
    if (i < N4_X) { s = x; d = xr; k = i; }
    else if (i < N4_X + N4_WQ) { s = wq; d = wqr; k = i - N4_X; }
    else { s = wo; d = wor; k = i - N4_X - N4_WQ; }
    const float4 v = s[k];
    uint4 w;
    w.x = f2tf32(v.x); w.y = f2tf32(v.y); w.z = f2tf32(v.z); w.w = f2tf32(v.w);
    d[k] = *(const float4*)&w;
}

// ---------------------------------------------------------------------------
// Bias expansion: g_bias[h][i][j] = biases[h][idxs[i][j]]
// ---------------------------------------------------------------------------
__global__ __launch_bounds__(256) void bias_expand_kernel(const float* __restrict__ biases,
                                                          const int* __restrict__ idxs) {
    const size_t t = (size_t)blockIdx.x * 256 + threadIdx.x;
    const int j = (int)(t & 255) * 4;
    const int i = (int)(t >> 8) & 1023;
    const int h = (int)(t >> 18);
    const int4 id = *(const int4*)&idxs[(size_t)i * NSEQ + j];
    const float* brow = biases + h * 1024;
    float4 o;
    o.x = __ldg(&brow[id.x]);
    o.y = __ldg(&brow[id.y]);
    o.z = __ldg(&brow[id.z]);
    o.w = __ldg(&brow[id.w]);
    *(float4*)&g_bias[((size_t)h << 20) + (size_t)i * NSEQ + j] = o;
}

// ===========================================================================
// tf32 GEMM: cp.async 3-stage ring + ldmatrix, BK=32. (unchanged from R7)
// ===========================================================================
#define STG_BYTES 32768

__device__ __forceinline__ uint32_t offG(int row, int u) {
    return (uint32_t)(row * 128 + ((u ^ (row & 7)) << 4));
}

__device__ __forceinline__ void tf32_mainloop_ca(const float* __restrict__ A,
                                                 const float* __restrict__ B,
                                                 int m0, int n0, char* sm,
                                                 float acc[4][4][4]) {
    const int tid = threadIdx.x;
    const int lane = tid & 31;
    const int wid = tid >> 5;
    const int wm = wid >> 2, wn = wid & 3;
    const uint32_t sb = smem_u32(sm);

    const int lrow = tid >> 3, lu = tid & 7;
    uint32_t oT[4];
    const float* ap[4];
    const float* bp[4];
#pragma unroll
    for (int i = 0; i < 4; i++) {
        const int row = lrow + 32 * i;
        oT[i] = offG(row, lu);
        ap[i] = A + (size_t)(m0 + row) * KDIM + lu * 4;
        bp[i] = B + (size_t)(n0 + row) * KDIM + lu * 4;
    }

#pragma unroll
    for (int i = 0; i < 4; i++)
#pragma unroll
        for (int j = 0; j < 4; j++)
#pragma unroll
            for (int r = 0; r < 4; r++) acc[i][j][r] = 0.f;

    const int sub = lane >> 3;
    const int arow = 64 * wm + (lane & 7) + ((sub & 1) << 3);
    const int aub = sub >> 1;
    const int brow = 32 * wn + (lane & 7) + ((sub >> 1) << 3);
    const int bub = sub & 1;
    const int asw = arow & 7;
    const int bsw = brow & 7;

#define G_ISSUE(st, p)                                                         \
    do {                                                                       \
        const int ko = (st) * 32;                                              \
        const uint32_t bb_ = sb + (uint32_t)(p) * STG_BYTES;                   \
        cpa16(bb_ + oT[0], ap[0] + ko);                                        \
        cpa16(bb_ + oT[1], ap[1] + ko);                                        \
        cpa16(bb_ + oT[2], ap[2] + ko);                                        \
        cpa16(bb_ + oT[3], ap[3] + ko);                                        \
        cpa16(bb_ + 16384 + oT[0], bp[0] + ko);                                \
        cpa16(bb_ + 16384 + oT[1], bp[1] + ko);                                \
        cpa16(bb_ + 16384 + oT[2], bp[2] + ko);                                \
        cpa16(bb_ + 16384 + oT[3], bp[3] + ko);                                \
    } while (0)

    G_ISSUE(0, 0);
    asm volatile("cp.async.commit_group;");
    G_ISSUE(1, 1);
    asm volatile("cp.async.commit_group;");

    const int NST = KDIM / 32;
    int p = 0;
    for (int st = 0; st < NST; st++) {
        asm volatile("cp.async.wait_group 1;");
        __syncthreads();
        const uint32_t abase = sb + (uint32_t)p * STG_BYTES;
        const uint32_t bbase = abase + 16384;
#pragma unroll
        for (int s = 0; s < 4; s++) {
            uint32_t af[4][4];
            uint32_t bf[4][2];
#pragma unroll
            for (int i = 0; i < 4; i++) {
                const int row = arow + 16 * i;
                ldsm4(af[i], abase + (uint32_t)(row * 128 + (((2 * s + aub) ^ asw) << 4)));
            }
#pragma unroll
            for (int jj = 0; jj < 2; jj++) {
                uint32_t t[4];
                const int row = brow + 16 * jj;
                ldsm4(t, bbase + (uint32_t)(row * 128 + (((2 * s + bub) ^ bsw) << 4)));
                bf[2 * jj][0] = t[0]; bf[2 * jj][1] = t[1];
                bf[2 * jj + 1][0] = t[2]; bf[2 * jj + 1][1] = t[3];
            }
#pragma unroll
            for (int i = 0; i < 4; i++)
#pragma unroll
                for (int j = 0; j < 4; j++)
                    mma_tf32(acc[i][j], af[i], bf[j]);
        }
        const int nx = st + 2;
        if (nx < NST) G_ISSUE(nx, nx % 3);
        asm volatile("cp.async.commit_group;");
        p = (p + 1) % 3;
    }
#undef G_ISSUE
}

// ---------------------------------------------------------------------------
// GEMM1: qkv scatter (unchanged)
// ---------------------------------------------------------------------------
__global__ __launch_bounds__(256) void qkv_gemm_mma(const float* __restrict__ A,
                                                    const float* __restrict__ W) {
    extern __shared__ char smg[];
    const int m0 = blockIdx.y * 128;
    const int n0 = blockIdx.x * 128;
    float acc[4][4][4];
    tf32_mainloop_ca(A, W, m0, n0, smg, acc);

    const int tid = threadIdx.x;
    const int lane = tid & 31;
    const int wid = tid >> 5;
    const int wm = wid >> 2, wn = wid & 3;

    const int t = n0 >> 10;
    const float scale = (t == 0) ? 0.125f : 1.0f;
    float* dst = (t == 0) ? g_q : ((t == 1) ? g_k : g_v);

#pragma unroll
    for (int i = 0; i < 4; i++) {
#pragma unroll
        for (int j = 0; j < 4; j++) {
#pragma unroll
            for (int hh = 0; hh < 2; hh++) {
                const int m = m0 + 64 * wm + 16 * i + (lane >> 2) + 8 * hh;
                const int n = n0 + 32 * wn + 8 * j + 2 * (lane & 3);
                const int b = m >> 10, nn = m & 1023;
                const int e = n & 1023;
                const int h = e >> 6, d = e & 63;
                float2 o;
                o.x = __uint_as_float(f2tf32(acc[i][j][2 * hh + 0] * scale));
                o.y = __uint_as_float(f2tf32(acc[i][j][2 * hh + 1] * scale));
                *(float2*)&dst[(((size_t)b * HEADS + h) * NSEQ + nn) * DHEAD + d] = o;
            }
        }
    }
}

// ---------------------------------------------------------------------------
// GEMM2: out-proj (unchanged)
// ---------------------------------------------------------------------------
__global__ __launch_bounds__(256) void out_gemm_mma(const float* __restrict__ W,
                                                    const float* __restrict__ bias,
                                                    float* __restrict__ out) {
    extern __shared__ char smg[];
    const int m0 = blockIdx.y * 128;
    const int n0 = blockIdx.x * 128;
    float acc[4][4][4];
    tf32_mainloop_ca(g_att, W, m0, n0, smg, acc);

    const int tid = threadIdx.x;
    const int lane = tid & 31;
    const int wid = tid >> 5;
    const int wm = wid >> 2, wn = wid & 3;

#pragma unroll
    for (int i = 0; i < 4; i++) {
#pragma unroll
        for (int j = 0; j < 4; j++) {
#pragma unroll
            for (int hh = 0; hh < 2; hh++) {
                const int m = m0 + 64 * wm + 16 * i + (lane >> 2) + 8 * hh;
                const int n = n0 + 32 * wn + 8 * j + 2 * (lane & 3);
                float2 o;
                o.x = acc[i][j][2 * hh + 0] + bias[n + 0];
                o.y = acc[i][j][2 * hh + 1] + bias[n + 1];
                *(float2*)&out[(size_t)m * EMBD + n] = o;
            }
        }
    }
}

// ===========================================================================
// Attention: 128-row Q tile, 8 warps = 4 row-groups (32 rows) x 2 halves.
// QK: warp = 32 rows x 32 keys (0.5 ldsm/MMA). PV: warp = 32 rows x 32 d
// over ALL 64 keys (0.5 ldsm/MMA, no O-combine). Direct exp, deferred sums.
// SMEM: Q 0..32K | K db 32..64K | VT 64..80K | P 80..112K | LS 112..113K
// ===========================================================================
#define ATT_Q 0u
#define ATT_K0 32768u
#define ATT_V 65536u
#define ATT_P 81920u
#define ATT_LS 114688u
#define ATT_SMEM 115712

__device__ __forceinline__ uint32_t off8(int row, int u) {
    return (uint32_t)(row * 256 + ((u ^ (row & 7)) << 4));
}

__global__ __launch_bounds__(256, 2) void attn_mma() {
    extern __shared__ char smc[];
    const uint32_t sb = smem_u32(smc);
    const int tid = threadIdx.x;
    const int lane = tid & 31;
    const int w = tid >> 5;
    const int wr = w >> 1;          // row-group (32 rows)
    const int wk = w & 1;           // key/d half
    const int g = lane >> 2;
    const int tig = lane & 3;

    const int q0 = blockIdx.x << 7;
    const int h = blockIdx.y & 15;
    const int b = blockIdx.y >> 4;

    const size_t bh = (size_t)(b * HEADS + h) * NSEQ * DHEAD;
    const float* qb = g_q + bh;
    const float* kb = g_k + bh;
    const float* vb = g_v + bh;

    // ---- Q tile via cp.async (once): 128 rows x 16 units ----
#pragma unroll
    for (int i = 0; i < 8; i++) {
        const int slot = tid + 256 * i;
        const int row = slot >> 4, lu = slot & 15;
        cpa16(sb + ATT_Q + off8(row, lu), qb + (size_t)(q0 + row) * DHEAD + lu * 4);
    }
    // ---- K0 ----
#pragma unroll
    for (int i = 0; i < 4; i++) {
        const int slot = tid + 256 * i;
        const int row = slot >> 4, lu = slot & 15;
        cpa16(sb + ATT_K0 + off8(row, lu), kb + (size_t)row * DHEAD + lu * 4);
    }
    asm volatile("cp.async.commit_group;");
    // ---- V0 LDG -> STS (transposed) ----
#pragma unroll
    for (int i = 0; i < 4; i++) {
        const int slot = tid + 256 * i;
        const int key = slot >> 4;
        const int d0 = (slot & 15) * 4;
        const float4 vv = *(const float4*)(vb + (size_t)key * DHEAD + d0);
        const uint32_t cu = (uint32_t)(key >> 2);
        const uint32_t co = (uint32_t)((key & 3) * 4);
        *(float*)(smc + ATT_V + off8(d0 + 0, cu) + co) = vv.x;
        *(float*)(smc + ATT_V + off8(d0 + 1, cu) + co) = vv.y;
        *(float*)(smc + ATT_V + off8(d0 + 2, cu) + co) = vv.z;
        *(float*)(smc + ATT_V + off8(d0 + 3, cu) + co) = vv.w;
    }

    float oc[2][4][4];
#pragma unroll
    for (int i = 0; i < 2; i++)
#pragma unroll
        for (int j = 0; j < 4; j++)
#pragma unroll
            for (int r = 0; r < 4; r++) oc[i][j][r] = 0.f;
    float ls[2][2] = {{0.f, 0.f}, {0.f, 0.f}};

    // bias base for this thread's rows (block i adds 16i, upper half +8)
    const float* btb = g_bias + ((size_t)h << 20) + (size_t)(q0 + 32 * wr + g) * NSEQ;

    // ldsm lane constants
    const int sub = lane >> 3;
    const int aub = sub >> 1;
    const int bub = sub & 1;
    const int arow0 = 32 * wr + (lane & 7) + ((sub & 1) << 3);   // +16 for block 1
    const int arow1 = arow0 + 16;
    const int asw0 = arow0 & 7;
    const int asw1 = arow1 & 7;
    const int krow = 32 * wk + (lane & 7) + ((sub >> 1) << 3);   // K and VT b rows (+16jj)

    for (int j0 = 0; j0 < NSEQ; j0 += 64) {
        const int p = (j0 >> 6) & 1;
        const uint32_t kcur = ATT_K0 + (uint32_t)p * 16384u;
        const uint32_t knxt = ATT_K0 + (uint32_t)(p ^ 1) * 16384u;
        const bool more = (j0 + 64 < NSEQ);
        if (more) {
#pragma unroll
            for (int i = 0; i < 4; i++) {
                const int slot = tid + 256 * i;
                const int row = slot >> 4, lu = slot & 15;
                cpa16(sb + knxt + off8(row, lu),
                      kb + (size_t)(j0 + 64 + row) * DHEAD + lu * 4);
            }
        }
        asm volatile("cp.async.commit_group;");
        float4 vv2[4];
        const int jv = more ? j0 + 64 : j0;
#pragma unroll
        for (int i = 0; i < 4; i++) {
            const int slot = tid + 256 * i;
            const int key = slot >> 4;
            const int d0 = (slot & 15) * 4;
            vv2[i] = *(const float4*)(vb + (size_t)(jv + key) * DHEAD + d0);
        }
        asm volatile("cp.async.wait_group 1;");
        __syncthreads();   // K(j) ready; VT(j) visible

        // ---- S = Q K^T : 32 rows x 32 keys per warp ----
        float sc[2][4][4];
#pragma unroll
        for (int i = 0; i < 2; i++)
#pragma unroll
            for (int j = 0; j < 4; j++)
#pragma unroll
                for (int r = 0; r < 4; r++) sc[i][j][r] = 0.f;
#pragma unroll
        for (int s = 0; s < 8; s++) {
            uint32_t a0[4], a1[4];
            ldsm4(a0, sb + ATT_Q + (uint32_t)(arow0 * 256 + (((2 * s + aub) ^ asw0) << 4)));
            ldsm4(a1, sb + ATT_Q + (uint32_t)(arow1 * 256 + (((2 * s + aub) ^ asw1) << 4)));
            uint32_t bf[4][2];
#pragma unroll
            for (int jj = 0; jj < 2; jj++) {
                uint32_t t[4];
                const int row = krow + 16 * jj;
                ldsm4(t, sb + kcur + (uint32_t)(row * 256 + (((2 * s + bub) ^ (row & 7)) << 4)));
                bf[2 * jj][0] = t[0]; bf[2 * jj][1] = t[1];
                bf[2 * jj + 1][0] = t[2]; bf[2 * jj + 1][1] = t[3];
            }
#pragma unroll
            for (int j = 0; j < 4; j++) {
                mma_tf32(sc[0][j], a0, bf[j]);
                mma_tf32(sc[1][j], a1, bf[j]);
            }
        }

        // ---- bias + exp + partial sums + P store (rows 32wr.., keys 32wk..) ----
#pragma unroll
        for (int i = 0; i < 2; i++) {
            const float* bt0 = btb + (size_t)(16 * i) * NSEQ;
            const float* bt1 = bt0 + 8 * NSEQ;
            const int pr0 = 32 * wr + 16 * i + g;
            const int pr1 = pr0 + 8;
            const uint32_t phalf = (uint32_t)((tig & 1) * 8);
#pragma unroll
            for (int u = 0; u < 4; u++) {
                const int cc = j0 + 32 * wk + 8 * u + 2 * tig;
                const float2 b0 = *(const float2*)(bt0 + cc);
                const float2 b1 = *(const float2*)(bt1 + cc);
                const float e0 = __expf(sc[i][u][0] + b0.x);
                const float e1 = __expf(sc[i][u][1] + b0.y);
                const float e2 = __expf(sc[i][u][2] + b1.x);
                const float e3 = __expf(sc[i][u][3] + b1.y);
                ls[i][0] += e0 + e1;
                ls[i][1] += e2 + e3;
                const int lu = 8 * wk + 2 * u + (tig >> 1);
                const uint32_t a0 = sb + ATT_P + off8(pr0, lu) + phalf;
                const uint32_t a1 = sb + ATT_P + off8(pr1, lu) + phalf;
                asm volatile("st.shared.v2.b32 [%0], {%1,%2};"
                             :: "r"(a0), "r"(f2tf32(e0)), "r"(f2tf32(e1)));
                asm volatile("st.shared.v2.b32 [%0], {%1,%2};"
                             :: "r"(a1), "r"(f2tf32(e2)), "r"(f2tf32(e3)));
            }
        }
        __syncthreads();   // P complete (cross-warp: PV reads both key halves)

        // ---- O += P V : 32 rows x 32 d per warp, all 64 keys ----
#pragma unroll
        for (int s = 0; s < 8; s++) {
            uint32_t a0[4], a1[4];
            ldsm4(a0, sb + ATT_P + (uint32_t)(arow0 * 256 + (((2 * s + aub) ^ asw0) << 4)));
            ldsm4(a1, sb + ATT_P + (uint32_t)(arow1 * 256 + (((2 * s + aub) ^ asw1) << 4)));
            uint32_t bf[4][2];
#pragma unroll
            for (int jj = 0; jj < 2; jj++) {
                uint32_t t[4];
                const int row = krow + 16 * jj;   // VT d rows 32wk..
                ldsm4(t, sb + ATT_V + (uint32_t)(row * 256 + (((2 * s + bub) ^ (row & 7)) << 4)));
                bf[2 * jj][0] = t[0]; bf[2 * jj][1] = t[1];
                bf[2 * jj + 1][0] = t[2]; bf[2 * jj + 1][1] = t[3];
            }
#pragma unroll
            for (int j = 0; j < 4; j++) {
                mma_tf32(oc[0][j], a0, bf[j]);
                mma_tf32(oc[1][j], a1, bf[j]);
            }
        }
        __syncthreads();   // VT / P reads done before overwrite

        // ---- store prefetched V(j+1) ----
#pragma unroll
        for (int i = 0; i < 4; i++) {
            const int slot = tid + 256 * i;
            const int key = slot >> 4;
            const int d0 = (slot & 15) * 4;
            const uint32_t cu = (uint32_t)(key >> 2);
            const uint32_t co = (uint32_t)((key & 3) * 4);
            *(float*)(smc + ATT_V + off8(d0 + 0, cu) + co) = vv2[i].x;
            *(float*)(smc + ATT_V + off8(d0 + 1, cu) + co) = vv2[i].y;
            *(float*)(smc + ATT_V + off8(d0 + 2, cu) + co) = vv2[i].z;
            *(float*)(smc + ATT_V + off8(d0 + 3, cu) + co) = vv2[i].w;
        }
    }

    // ---- row-sum combine across key halves ----
#pragma unroll
    for (int i = 0; i < 2; i++) {
#pragma unroll
        for (int r = 0; r < 2; r++) {
            ls[i][r] += __shfl_xor_sync(0xFFFFFFFFu, ls[i][r], 1);
            ls[i][r] += __shfl_xor_sync(0xFFFFFFFFu, ls[i][r], 2);
        }
    }
    float* lsb = (float*)(smc + ATT_LS);   // [2][128]
    if (tig == 0) {
#pragma unroll
        for (int i = 0; i < 2; i++) {
            lsb[wk * 128 + 32 * wr + 16 * i + g] = ls[i][0];
            lsb[wk * 128 + 32 * wr + 16 * i + g + 8] = ls[i][1];
        }
    }
    __syncthreads();

    // ---- normalize + write (rows 32wr.., d 32wk..) ----
#pragma unroll
    for (int i = 0; i < 2; i++) {
        const int r0 = 32 * wr + 16 * i + g;
        const float inv0 = 1.f / (lsb[r0] + lsb[128 + r0]);
        const float inv1 = 1.f / (lsb[r0 + 8] + lsb[128 + r0 + 8]);
        const int grow = q0 + r0;
#pragma unroll
        for (int j = 0; j < 4; j++) {
            const int d = 32 * wk + 8 * j + 2 * tig;
            float2 o0, o1;
            o0.x = __uint_as_float(f2tf32(oc[i][j][0] * inv0));
            o0.y = __uint_as_float(f2tf32(oc[i][j][1] * inv0));
            o1.x = __uint_as_float(f2tf32(oc[i][j][2] * inv1));
            o1.y = __uint_as_float(f2tf32(oc[i][j][3] * inv1));
            *(float2*)&g_att[((size_t)b * NSEQ + grow) * EMBD + h * DHEAD + d] = o0;
            *(float2*)&g_att[((size_t)b * NSEQ + grow + 8) * EMBD + h * DHEAD + d] = o1;
        }
    }
}

// ---------------------------------------------------------------------------
extern "C" void kernel_launch(void* const* d_in, const int* in_sizes, int n_in,
                              void* d_out, int out_size) {
    (void)in_sizes; (void)n_in; (void)out_size;
    const float* x      = (const float*)d_in[0];
    const float* W_qkv  = (const float*)d_in[1];
    const float* biases = (const float*)d_in[2];
    const int*   idxs   = (const int*)d_in[3];
    const float* W_out  = (const float*)d_in[4];
    const float* b_out  = (const float*)d_in[5];
    float* out = (float*)d_out;

    float* xr;  cudaGetSymbolAddress((void**)&xr, g_xr);
    float* wqr; cudaGetSymbolAddress((void**)&wqr, g_wqr);
    float* wor; cudaGetSymbolAddress((void**)&wor, g_wor);

    const int gemm_smem = 3 * STG_BYTES;   // 96 KB
    cudaFuncSetAttribute(qkv_gemm_mma, cudaFuncAttributeMaxDynamicSharedMemorySize, gemm_smem);
    cudaFuncSetAttribute(out_gemm_mma, cudaFuncAttributeMaxDynamicSharedMemorySize, gemm_smem);
    cudaFuncSetAttribute(attn_mma, cudaFuncAttributeMaxDynamicSharedMemorySize, ATT_SMEM);

    const int n4_total = N4_X + N4_WQ + N4_WO;
    round_all_kernel<<<(n4_total + 255) / 256, 256>>>(
        (const float4*)x, (const float4*)W_qkv, (const float4*)W_out,
        (float4*)xr, (float4*)wqr, (float4*)wor);
    bias_expand_kernel<<<(HEADS * NSEQ * NSEQ / 4) / 256, 256>>>(biases, idxs);

    qkv_gemm_mma<<<dim3(24, 64), 256, gemm_smem>>>(xr, wqr);
    attn_mma<<<dim3(8, BATCHX * HEADS), 256, ATT_SMEM>>>();
    out_gemm_mma<<<dim3(8, 64), 256, gemm_smem>>>(wor, b_out, out);
}

// round 16
// speedup vs baseline: 1.1214x; 1.0148x over previous
#include <cuda_runtime.h>
#include <cstdint>

// Problem constants
#define BATCHX 8
#define NSEQ   1024
#define EMBD   1024
#define HEADS  16
#define DHEAD  64
#define KDIM   1024
#define MROWS  (BATCHX * NSEQ)   // 8192

// Scratch (device globals: allocation-free per harness rules)
__device__ float g_q[BATCHX * HEADS * NSEQ * DHEAD];
__device__ float g_k[BATCHX * HEADS * NSEQ * DHEAD];
__device__ float g_v[BATCHX * HEADS * NSEQ * DHEAD];
__device__ float g_att[MROWS * EMBD];
__device__ float g_xr[MROWS * EMBD];
__device__ float g_wqr[3 * EMBD * EMBD];
__device__ float g_wor[EMBD * EMBD];
__device__ float g_bias[HEADS * NSEQ * NSEQ];

__device__ __forceinline__ uint32_t smem_u32(const void* p) {
    uint32_t a;
    asm("{ .reg .u64 t; cvta.to.shared.u64 t, %1; cvt.u32.u64 %0, t; }"
        : "=r"(a) : "l"(p));
    return a;
}

__device__ __forceinline__ uint32_t f2tf32(float x) {
    uint32_t y;
    asm("cvt.rna.tf32.f32 %0, %1;" : "=r"(y) : "f"(x));
    return y;
}

__device__ __forceinline__ void mma_tf32(float* c, const uint32_t* a, const uint32_t* b) {
    asm volatile(
        "mma.sync.aligned.m16n8k8.row.col.f32.tf32.tf32.f32 "
        "{%0,%1,%2,%3}, {%4,%5,%6,%7}, {%8,%9}, {%0,%1,%2,%3};"
        : "+f"(c[0]), "+f"(c[1]), "+f"(c[2]), "+f"(c[3])
        : "r"(a[0]), "r"(a[1]), "r"(a[2]), "r"(a[3]), "r"(b[0]), "r"(b[1]));
}

__device__ __forceinline__ void ldsm4(uint32_t* r, uint32_t addr) {
    asm volatile("ldmatrix.sync.aligned.m8n8.x4.shared.b16 {%0,%1,%2,%3}, [%4];"
                 : "=r"(r[0]), "=r"(r[1]), "=r"(r[2]), "=r"(r[3]) : "r"(addr));
}

__device__ __forceinline__ void cpa16(uint32_t dst, const void* src) {
    asm volatile("cp.async.cg.shared.global [%0], [%1], 16;" :: "r"(dst), "l"(src));
}

// ---------------------------------------------------------------------------
// Fused tf32 pre-round pass
// ---------------------------------------------------------------------------
#define N4_X  (MROWS * EMBD / 4)
#define N4_WQ (3 * EMBD * EMBD / 4)
#define N4_WO (EMBD * EMBD / 4)

__global__ __launch_bounds__(256) void round_all_kernel(const float4* __restrict__ x,
                                                        const float4* __restrict__ wq,
                                                        const float4* __restrict__ wo,
                                                        float4* __restrict__ xr,
                                                        float4* __restrict__ wqr,
                                                        float4* __restrict__ wor) {
    const int i = blockIdx.x * 256 + threadIdx.x;
    const float4* s;
    float4* d;
    int k;
    if (i < N4_X) { s = x; d = xr; k = i; }
    else if (i < N4_X + N4_WQ) { s = wq; d = wqr; k = i - N4_X; }
    else { s = wo; d = wor; k = i - N4_X - N4_WQ; }
    const float4 v = s[k];
    uint4 w;
    w.x = f2tf32(v.x); w.y = f2tf32(v.y); w.z = f2tf32(v.z); w.w = f2tf32(v.w);
    d[k] = *(const float4*)&w;
}

// ---------------------------------------------------------------------------
// Bias expansion: g_bias[h][i][j] = biases[h][idxs[i][j]]
// ---------------------------------------------------------------------------
__global__ __launch_bounds__(256) void bias_expand_kernel(const float* __restrict__ biases,
                                                          const int* __restrict__ idxs) {
    const size_t t = (size_t)blockIdx.x * 256 + threadIdx.x;
    const int j = (int)(t & 255) * 4;
    const int i = (int)(t >> 8) & 1023;
    const int h = (int)(t >> 18);
    const int4 id = *(const int4*)&idxs[(size_t)i * NSEQ + j];
    const float* brow = biases + h * 1024;
    float4 o;
    o.x = __ldg(&brow[id.x]);
    o.y = __ldg(&brow[id.y]);
    o.z = __ldg(&brow[id.z]);
    o.w = __ldg(&brow[id.w]);
    *(float4*)&g_bias[((size_t)h << 20) + (size_t)i * NSEQ + j] = o;
}

// ===========================================================================
// tf32 GEMM: cp.async 3-stage ring + ldmatrix, BK=32. (unchanged from R7)
// ===========================================================================
#define STG_BYTES 32768

__device__ __forceinline__ uint32_t offG(int row, int u) {
    return (uint32_t)(row * 128 + ((u ^ (row & 7)) << 4));
}

__device__ __forceinline__ void tf32_mainloop_ca(const float* __restrict__ A,
                                                 const float* __restrict__ B,
                                                 int m0, int n0, char* sm,
                                                 float acc[4][4][4]) {
    const int tid = threadIdx.x;
    const int lane = tid & 31;
    const int wid = tid >> 5;
    const int wm = wid >> 2, wn = wid & 3;
    const uint32_t sb = smem_u32(sm);

    const int lrow = tid >> 3, lu = tid & 7;
    uint32_t oT[4];
    const float* ap[4];
    const float* bp[4];
#pragma unroll
    for (int i = 0; i < 4; i++) {
        const int row = lrow + 32 * i;
        oT[i] = offG(row, lu);
        ap[i] = A + (size_t)(m0 + row) * KDIM + lu * 4;
        bp[i] = B + (size_t)(n0 + row) * KDIM + lu * 4;
    }

#pragma unroll
    for (int i = 0; i < 4; i++)
#pragma unroll
        for (int j = 0; j < 4; j++)
#pragma unroll
            for (int r = 0; r < 4; r++) acc[i][j][r] = 0.f;

    const int sub = lane >> 3;
    const int arow = 64 * wm + (lane & 7) + ((sub & 1) << 3);
    const int aub = sub >> 1;
    const int brow = 32 * wn + (lane & 7) + ((sub >> 1) << 3);
    const int bub = sub & 1;
    const int asw = arow & 7;
    const int bsw = brow & 7;

#define G_ISSUE(st, p)                                                         \
    do {                                                                       \
        const int ko = (st) * 32;                                              \
        const uint32_t bb_ = sb + (uint32_t)(p) * STG_BYTES;                   \
        cpa16(bb_ + oT[0], ap[0] + ko);                                        \
        cpa16(bb_ + oT[1], ap[1] + ko);                                        \
        cpa16(bb_ + oT[2], ap[2] + ko);                                        \
        cpa16(bb_ + oT[3], ap[3] + ko);                                        \
        cpa16(bb_ + 16384 + oT[0], bp[0] + ko);                                \
        cpa16(bb_ + 16384 + oT[1], bp[1] + ko);                                \
        cpa16(bb_ + 16384 + oT[2], bp[2] + ko);                                \
        cpa16(bb_ + 16384 + oT[3], bp[3] + ko);                                \
    } while (0)

    G_ISSUE(0, 0);
    asm volatile("cp.async.commit_group;");
    G_ISSUE(1, 1);
    asm volatile("cp.async.commit_group;");

    const int NST = KDIM / 32;
    int p = 0;
    for (int st = 0; st < NST; st++) {
        asm volatile("cp.async.wait_group 1;");
        __syncthreads();
        const uint32_t abase = sb + (uint32_t)p * STG_BYTES;
        const uint32_t bbase = abase + 16384;
#pragma unroll
        for (int s = 0; s < 4; s++) {
            uint32_t af[4][4];
            uint32_t bf[4][2];
#pragma unroll
            for (int i = 0; i < 4; i++) {
                const int row = arow + 16 * i;
                ldsm4(af[i], abase + (uint32_t)(row * 128 + (((2 * s + aub) ^ asw) << 4)));
            }
#pragma unroll
            for (int jj = 0; jj < 2; jj++) {
                uint32_t t[4];
                const int row = brow + 16 * jj;
                ldsm4(t, bbase + (uint32_t)(row * 128 + (((2 * s + bub) ^ bsw) << 4)));
                bf[2 * jj][0] = t[0]; bf[2 * jj][1] = t[1];
                bf[2 * jj + 1][0] = t[2]; bf[2 * jj + 1][1] = t[3];
            }
#pragma unroll
            for (int i = 0; i < 4; i++)
#pragma unroll
                for (int j = 0; j < 4; j++)
                    mma_tf32(acc[i][j], af[i], bf[j]);
        }
        const int nx = st + 2;
        if (nx < NST) G_ISSUE(nx, nx % 3);
        asm volatile("cp.async.commit_group;");
        p = (p + 1) % 3;
    }
#undef G_ISSUE
}

// ---------------------------------------------------------------------------
// GEMM1: qkv scatter (unchanged)
// ---------------------------------------------------------------------------
__global__ __launch_bounds__(256) void qkv_gemm_mma(const float* __restrict__ A,
                                                    const float* __restrict__ W) {
    extern __shared__ char smg[];
    const int m0 = blockIdx.y * 128;
    const int n0 = blockIdx.x * 128;
    float acc[4][4][4];
    tf32_mainloop_ca(A, W, m0, n0, smg, acc);

    const int tid = threadIdx.x;
    const int lane = tid & 31;
    const int wid = tid >> 5;
    const int wm = wid >> 2, wn = wid & 3;

    const int t = n0 >> 10;
    const float scale = (t == 0) ? 0.125f : 1.0f;
    float* dst = (t == 0) ? g_q : ((t == 1) ? g_k : g_v);

#pragma unroll
    for (int i = 0; i < 4; i++) {
#pragma unroll
        for (int j = 0; j < 4; j++) {
#pragma unroll
            for (int hh = 0; hh < 2; hh++) {
                const int m = m0 + 64 * wm + 16 * i + (lane >> 2) + 8 * hh;
                const int n = n0 + 32 * wn + 8 * j + 2 * (lane & 3);
                const int b = m >> 10, nn = m & 1023;
                const int e = n & 1023;
                const int h = e >> 6, d = e & 63;
                float2 o;
                o.x = __uint_as_float(f2tf32(acc[i][j][2 * hh + 0] * scale));
                o.y = __uint_as_float(f2tf32(acc[i][j][2 * hh + 1] * scale));
                *(float2*)&dst[(((size_t)b * HEADS + h) * NSEQ + nn) * DHEAD + d] = o;
            }
        }
    }
}

// ---------------------------------------------------------------------------
// GEMM2: out-proj (unchanged)
// ---------------------------------------------------------------------------
__global__ __launch_bounds__(256) void out_gemm_mma(const float* __restrict__ W,
                                                    const float* __restrict__ bias,
                                                    float* __restrict__ out) {
    extern __shared__ char smg[];
    const int m0 = blockIdx.y * 128;
    const int n0 = blockIdx.x * 128;
    float acc[4][4][4];
    tf32_mainloop_ca(g_att, W, m0, n0, smg, acc);

    const int tid = threadIdx.x;
    const int lane = tid & 31;
    const int wid = tid >> 5;
    const int wm = wid >> 2, wn = wid & 3;

#pragma unroll
    for (int i = 0; i < 4; i++) {
#pragma unroll
        for (int j = 0; j < 4; j++) {
#pragma unroll
            for (int hh = 0; hh < 2; hh++) {
                const int m = m0 + 64 * wm + 16 * i + (lane >> 2) + 8 * hh;
                const int n = n0 + 32 * wn + 8 * j + 2 * (lane & 3);
                float2 o;
                o.x = acc[i][j][2 * hh + 0] + bias[n + 0];
                o.y = acc[i][j][2 * hh + 1] + bias[n + 1];
                *(float2*)&out[(size_t)m * EMBD + n] = o;
            }
        }
    }
}

// ===========================================================================
// Attention (R14 structure) + Gray-code V path:
// VT[d][key] with unit swizzle S(d) = (d ^ (d>>1)) & 7 and loader mapping
// key=(slot&7)+8*(slot>>7), dchunk=(slot>>3)&15 -> conflict-free V stores
// AND conflict-free PV ldsm (S bijective on any aligned-8 d rows).
// ===========================================================================
#define ATT_Q 0u
#define ATT_K0 32768u
#define ATT_V 65536u
#define ATT_P 81920u
#define ATT_LS 114688u
#define ATT_SMEM 115712

__device__ __forceinline__ uint32_t off8(int row, int u) {
    return (uint32_t)(row * 256 + ((u ^ (row & 7)) << 4));
}

// V transpose store: element (d, key) -> Gray-swizzled unit
__device__ __forceinline__ uint32_t offV(int d, int key) {
    const int u = (key >> 2) ^ ((d ^ (d >> 1)) & 7);
    return (uint32_t)(d * 256 + u * 16 + (key & 3) * 4);
}

__global__ __launch_bounds__(256, 2) void attn_mma() {
    extern __shared__ char smc[];
    const uint32_t sb = smem_u32(smc);
    const int tid = threadIdx.x;
    const int lane = tid & 31;
    const int w = tid >> 5;
    const int wr = w >> 1;          // row-group (32 rows)
    const int wk = w & 1;           // key/d half
    const int g = lane >> 2;
    const int tig = lane & 3;

    const int q0 = blockIdx.x << 7;
    const int h = blockIdx.y & 15;
    const int b = blockIdx.y >> 4;

    const size_t bh = (size_t)(b * HEADS + h) * NSEQ * DHEAD;
    const float* qb = g_q + bh;
    const float* kb = g_k + bh;
    const float* vb = g_v + bh;

    // ---- Q tile via cp.async (once): 128 rows x 16 units ----
#pragma unroll
    for (int i = 0; i < 8; i++) {
        const int slot = tid + 256 * i;
        const int row = slot >> 4, lu = slot & 15;
        cpa16(sb + ATT_Q + off8(row, lu), qb + (size_t)(q0 + row) * DHEAD + lu * 4);
    }
    // ---- K0 ----
#pragma unroll
    for (int i = 0; i < 4; i++) {
        const int slot = tid + 256 * i;
        const int row = slot >> 4, lu = slot & 15;
        cpa16(sb + ATT_K0 + off8(row, lu), kb + (size_t)row * DHEAD + lu * 4);
    }
    asm volatile("cp.async.commit_group;");
    // ---- V0 LDG -> STS (Gray-swizzled transpose, conflict-free) ----
#pragma unroll
    for (int i = 0; i < 4; i++) {
        const int slot = tid + 256 * i;
        const int key = (slot & 7) + 8 * (slot >> 7);
        const int dc = (slot >> 3) & 15;
        const float4 vv = *(const float4*)(vb + (size_t)key * DHEAD + dc * 4);
        *(float*)(smc + ATT_V + offV(dc * 4 + 0, key)) = vv.x;
        *(float*)(smc + ATT_V + offV(dc * 4 + 1, key)) = vv.y;
        *(float*)(smc + ATT_V + offV(dc * 4 + 2, key)) = vv.z;
        *(float*)(smc + ATT_V + offV(dc * 4 + 3, key)) = vv.w;
    }

    float oc[2][4][4];
#pragma unroll
    for (int i = 0; i < 2; i++)
#pragma unroll
        for (int j = 0; j < 4; j++)
#pragma unroll
            for (int r = 0; r < 4; r++) oc[i][j][r] = 0.f;
    float ls[2][2] = {{0.f, 0.f}, {0.f, 0.f}};

    const float* btb = g_bias + ((size_t)h << 20) + (size_t)(q0 + 32 * wr + g) * NSEQ;

    // ldsm lane constants
    const int sub = lane >> 3;
    const int aub = sub >> 1;
    const int bub = sub & 1;
    const int arow0 = 32 * wr + (lane & 7) + ((sub & 1) << 3);
    const int arow1 = arow0 + 16;
    const int asw0 = arow0 & 7;
    const int asw1 = arow1 & 7;
    const int krow = 32 * wk + (lane & 7) + ((sub >> 1) << 3);   // K rows / VT d rows (+16jj)
    const int vsw = (krow ^ (krow >> 1)) & 7;   // Gray swizzle; invariant under +16

    for (int j0 = 0; j0 < NSEQ; j0 += 64) {
        const int p = (j0 >> 6) & 1;
        const uint32_t kcur = ATT_K0 + (uint32_t)p * 16384u;
        const uint32_t knxt = ATT_K0 + (uint32_t)(p ^ 1) * 16384u;
        const bool more = (j0 + 64 < NSEQ);
        if (more) {
#pragma unroll
            for (int i = 0; i < 4; i++) {
                const int slot = tid + 256 * i;
                const int row = slot >> 4, lu = slot & 15;
                cpa16(sb + knxt + off8(row, lu),
                      kb + (size_t)(j0 + 64 + row) * DHEAD + lu * 4);
            }
        }
        asm volatile("cp.async.commit_group;");
        float4 vv2[4];
        const int jv = more ? j0 + 64 : j0;
#pragma unroll
        for (int i = 0; i < 4; i++) {
            const int slot = tid + 256 * i;
            const int key = (slot & 7) + 8 * (slot >> 7);
            const int dc = (slot >> 3) & 15;
            vv2[i] = *(const float4*)(vb + (size_t)(jv + key) * DHEAD + dc * 4);
        }
        asm volatile("cp.async.wait_group 1;");
        __syncthreads();   // K(j) ready; VT(j) visible

        // ---- S = Q K^T : 32 rows x 32 keys per warp ----
        float sc[2][4][4];
#pragma unroll
        for (int i = 0; i < 2; i++)
#pragma unroll
            for (int j = 0; j < 4; j++)
#pragma unroll
                for (int r = 0; r < 4; r++) sc[i][j][r] = 0.f;
#pragma unroll
        for (int s = 0; s < 8; s++) {
            uint32_t a0[4], a1[4];
            ldsm4(a0, sb + ATT_Q + (uint32_t)(arow0 * 256 + (((2 * s + aub) ^ asw0) << 4)));
            ldsm4(a1, sb + ATT_Q + (uint32_t)(arow1 * 256 + (((2 * s + aub) ^ asw1) << 4)));
            uint32_t bf[4][2];
#pragma unroll
            for (int jj = 0; jj < 2; jj++) {
                uint32_t t[4];
                const int row = krow + 16 * jj;
                ldsm4(t, sb + kcur + (uint32_t)(row * 256 + (((2 * s + bub) ^ (row & 7)) << 4)));
                bf[2 * jj][0] = t[0]; bf[2 * jj][1] = t[1];
                bf[2 * jj + 1][0] = t[2]; bf[2 * jj + 1][1] = t[3];
            }
#pragma unroll
            for (int j = 0; j < 4; j++) {
                mma_tf32(sc[0][j], a0, bf[j]);
                mma_tf32(sc[1][j], a1, bf[j]);
            }
        }

        // ---- bias + exp + partial sums + P store ----
#pragma unroll
        for (int i = 0; i < 2; i++) {
            const float* bt0 = btb + (size_t)(16 * i) * NSEQ;
            const float* bt1 = bt0 + 8 * NSEQ;
            const int pr0 = 32 * wr + 16 * i + g;
            const int pr1 = pr0 + 8;
            const uint32_t phalf = (uint32_t)((tig & 1) * 8);
#pragma unroll
            for (int u = 0; u < 4; u++) {
                const int cc = j0 + 32 * wk + 8 * u + 2 * tig;
                const float2 b0 = *(const float2*)(bt0 + cc);
                const float2 b1 = *(const float2*)(bt1 + cc);
                const float e0 = __expf(sc[i][u][0] + b0.x);
                const float e1 = __expf(sc[i][u][1] + b0.y);
                const float e2 = __expf(sc[i][u][2] + b1.x);
                const float e3 = __expf(sc[i][u][3] + b1.y);
                ls[i][0] += e0 + e1;
                ls[i][1] += e2 + e3;
                const int lu = 8 * wk + 2 * u + (tig >> 1);
                const uint32_t a0 = sb + ATT_P + off8(pr0, lu) + phalf;
                const uint32_t a1 = sb + ATT_P + off8(pr1, lu) + phalf;
                asm volatile("st.shared.v2.b32 [%0], {%1,%2};"
                             :: "r"(a0), "r"(f2tf32(e0)), "r"(f2tf32(e1)));
                asm volatile("st.shared.v2.b32 [%0], {%1,%2};"
                             :: "r"(a1), "r"(f2tf32(e2)), "r"(f2tf32(e3)));
            }
        }
        __syncthreads();   // P complete (cross-warp)

        // ---- O += P V : 32 rows x 32 d per warp, all 64 keys ----
#pragma unroll
        for (int s = 0; s < 8; s++) {
            uint32_t a0[4], a1[4];
            ldsm4(a0, sb + ATT_P + (uint32_t)(arow0 * 256 + (((2 * s + aub) ^ asw0) << 4)));
            ldsm4(a1, sb + ATT_P + (uint32_t)(arow1 * 256 + (((2 * s + aub) ^ asw1) << 4)));
            uint32_t bf[4][2];
#pragma unroll
            for (int jj = 0; jj < 2; jj++) {
                uint32_t t[4];
                const int row = krow + 16 * jj;   // VT d rows
                ldsm4(t, sb + ATT_V + (uint32_t)(row * 256 + (((2 * s + bub) ^ vsw) << 4)));
                bf[2 * jj][0] = t[0]; bf[2 * jj][1] = t[1];
                bf[2 * jj + 1][0] = t[2]; bf[2 * jj + 1][1] = t[3];
            }
#pragma unroll
            for (int j = 0; j < 4; j++) {
                mma_tf32(oc[0][j], a0, bf[j]);
                mma_tf32(oc[1][j], a1, bf[j]);
            }
        }
        __syncthreads();   // VT / P reads done before overwrite

        // ---- store prefetched V(j+1), Gray-swizzled (conflict-free) ----
#pragma unroll
        for (int i = 0; i < 4; i++) {
            const int slot = tid + 256 * i;
            const int key = (slot & 7) + 8 * (slot >> 7);
            const int dc = (slot >> 3) & 15;
            *(float*)(smc + ATT_V + offV(dc * 4 + 0, key)) = vv2[i].x;
            *(float*)(smc + ATT_V + offV(dc * 4 + 1, key)) = vv2[i].y;
            *(float*)(smc + ATT_V + offV(dc * 4 + 2, key)) = vv2[i].z;
            *(float*)(smc + ATT_V + offV(dc * 4 + 3, key)) = vv2[i].w;
        }
    }

    // ---- row-sum combine across key halves ----
#pragma unroll
    for (int i = 0; i < 2; i++) {
#pragma unroll
        for (int r = 0; r < 2; r++) {
            ls[i][r] += __shfl_xor_sync(0xFFFFFFFFu, ls[i][r], 1);
            ls[i][r] += __shfl_xor_sync(0xFFFFFFFFu, ls[i][r], 2);
        }
    }
    float* lsb = (float*)(smc + ATT_LS);   // [2][128]
    if (tig == 0) {
#pragma unroll
        for (int i = 0; i < 2; i++) {
            lsb[wk * 128 + 32 * wr + 16 * i + g] = ls[i][0];
            lsb[wk * 128 + 32 * wr + 16 * i + g + 8] = ls[i][1];
        }
    }
    __syncthreads();

    // ---- normalize + write ----
#pragma unroll
    for (int i = 0; i < 2; i++) {
        const int r0 = 32 * wr + 16 * i + g;
        const float inv0 = 1.f / (lsb[r0] + lsb[128 + r0]);
        const float inv1 = 1.f / (lsb[r0 + 8] + lsb[128 + r0 + 8]);
        const int grow = q0 + r0;
#pragma unroll
        for (int j = 0; j < 4; j++) {
            const int d = 32 * wk + 8 * j + 2 * tig;
            float2 o0, o1;
            o0.x = __uint_as_float(f2tf32(oc[i][j][0] * inv0));
            o0.y = __uint_as_float(f2tf32(oc[i][j][1] * inv0));
            o1.x = __uint_as_float(f2tf32(oc[i][j][2] * inv1));
            o1.y = __uint_as_float(f2tf32(oc[i][j][3] * inv1));
            *(float2*)&g_att[((size_t)b * NSEQ + grow) * EMBD + h * DHEAD + d] = o0;
            *(float2*)&g_att[((size_t)b * NSEQ + grow + 8) * EMBD + h * DHEAD + d] = o1;
        }
    }
}

// ---------------------------------------------------------------------------
extern "C" void kernel_launch(void* const* d_in, const int* in_sizes, int n_in,
                              void* d_out, int out_size) {
    (void)in_sizes; (void)n_in; (void)out_size;
    const float* x      = (const float*)d_in[0];
    const float* W_qkv  = (const float*)d_in[1];
    const float* biases = (const float*)d_in[2];
    const int*   idxs   = (const int*)d_in[3];
    const float* W_out  = (const float*)d_in[4];
    const float* b_out  = (const float*)d_in[5];
    float* out = (float*)d_out;

    float* xr;  cudaGetSymbolAddress((void**)&xr, g_xr);
    float* wqr; cudaGetSymbolAddress((void**)&wqr, g_wqr);
    float* wor; cudaGetSymbolAddress((void**)&wor, g_wor);

    const int gemm_smem = 3 * STG_BYTES;   // 96 KB
    cudaFuncSetAttribute(qkv_gemm_mma, cudaFuncAttributeMaxDynamicSharedMemorySize, gemm_smem);
    cudaFuncSetAttribute(out_gemm_mma, cudaFuncAttributeMaxDynamicSharedMemorySize, gemm_smem);
    cudaFuncSetAttribute(attn_mma, cudaFuncAttributeMaxDynamicSharedMemorySize, ATT_SMEM);

    const int n4_total = N4_X + N4_WQ + N4_WO;
    round_all_kernel<<<(n4_total + 255) / 256, 256>>>(
        (const float4*)x, (const float4*)W_qkv, (const float4*)W_out,
        (float4*)xr, (float4*)wqr, (float4*)wor);
    bias_expand_kernel<<<(HEADS * NSEQ * NSEQ / 4) / 256, 256>>>(biases, idxs);

    qkv_gemm_mma<<<dim3(24, 64), 256, gemm_smem>>>(xr, wqr);
    attn_mma<<<dim3(8, BATCHX * HEADS), 256, ATT_SMEM>>>();
    out_gemm_mma<<<dim3(8, 64), 256, gemm_smem>>>(wor, b_out, out);
}